// round 1
// baseline (speedup 1.0000x reference)
#include <cuda_runtime.h>
#include <math_constants.h>

#define BB 4
#define CC 64
#define NN 8192
#define OO 128
#define KK 20
#define BN (BB*NN)

// ---------------- scratch (static device globals; no allocation) ----------------
__device__ float g_pd[268435456ull];     // [B*N, N] pairwise -dist^2   (1 GB)
__device__ float g_xt[(size_t)BN*CC];    // x transposed: [B*N, C]
__device__ float g_xx[BN];               // squared norms
__device__ float g_pt[(size_t)BN*256];   // per point: P[128] then T[128]
__device__ int   g_idx[(size_t)BN*KK];   // top-20 neighbor indices (order-free)

// ---------------- K0: transpose x + squared norms ----------------
__global__ __launch_bounds__(256) void k_prep(const float* __restrict__ x) {
    int g = blockIdx.x * 256 + threadIdx.x;      // g = b*N + n
    int b = g >> 13, n = g & (NN - 1);
    const float* xb = x + (size_t)b * CC * NN + n;
    float acc = 0.f;
#pragma unroll
    for (int c = 0; c < CC; c++) {
        float v = xb[(size_t)c * NN];
        acc = fmaf(v, v, acc);
        g_xt[(size_t)g * CC + c] = v;
    }
    g_xx[g] = acc;
}

// ---------------- K1: pd = 2*X^T X - xx_n - xx_m  (128x128 tile, K=64) ----------------
__global__ __launch_bounds__(256) void k_gemm(const float* __restrict__ x) {
    extern __shared__ float sm[];
    float* As = sm;               // [64][128]
    float* Bs = sm + 64 * 128;    // [64][128]
    int b = blockIdx.z;
    int n0 = blockIdx.y << 7, m0 = blockIdx.x << 7;
    const float* xb = x + (size_t)b * CC * NN;
    int t = threadIdx.x;
    for (int s = t; s < 64 * 128; s += 256) {
        int c = s >> 7, i = s & 127;
        As[s] = xb[(size_t)c * NN + n0 + i];
        Bs[s] = xb[(size_t)c * NN + m0 + i];
    }
    __syncthreads();

    int tx = t & 15, ty = t >> 4;
    float acc[8][8];
#pragma unroll
    for (int i = 0; i < 8; i++)
#pragma unroll
        for (int j = 0; j < 8; j++) acc[i][j] = 0.f;

#pragma unroll
    for (int c = 0; c < CC; c++) {
        float a[8], bb[8];
        *(float4*)&a[0]  = *(float4*)&As[c * 128 + ty * 8];
        *(float4*)&a[4]  = *(float4*)&As[c * 128 + ty * 8 + 4];
        *(float4*)&bb[0] = *(float4*)&Bs[c * 128 + tx * 8];
        *(float4*)&bb[4] = *(float4*)&Bs[c * 128 + tx * 8 + 4];
#pragma unroll
        for (int i = 0; i < 8; i++)
#pragma unroll
            for (int j = 0; j < 8; j++)
                acc[i][j] = fmaf(a[i], bb[j], acc[i][j]);
    }

    float xn[8], xm[8];
#pragma unroll
    for (int i = 0; i < 8; i++) xn[i] = g_xx[b * NN + n0 + ty * 8 + i];
#pragma unroll
    for (int j = 0; j < 8; j++) xm[j] = g_xx[b * NN + m0 + tx * 8 + j];

#pragma unroll
    for (int i = 0; i < 8; i++) {
        float4 o0, o1;
        o0.x = 2.f * acc[i][0] - xn[i] - xm[0];
        o0.y = 2.f * acc[i][1] - xn[i] - xm[1];
        o0.z = 2.f * acc[i][2] - xn[i] - xm[2];
        o0.w = 2.f * acc[i][3] - xn[i] - xm[3];
        o1.x = 2.f * acc[i][4] - xn[i] - xm[4];
        o1.y = 2.f * acc[i][5] - xn[i] - xm[5];
        o1.z = 2.f * acc[i][6] - xn[i] - xm[6];
        o1.w = 2.f * acc[i][7] - xn[i] - xm[7];
        size_t off = ((size_t)(b * NN + n0 + ty * 8 + i)) * NN + m0 + tx * 8;
        *(float4*)&g_pd[off]     = o0;
        *(float4*)&g_pd[off + 4] = o1;
    }
}

// ---------------- K2: top-20 per row (set semantics; order irrelevant) ----------------
__global__ __launch_bounds__(256) void k_topk() {
    __shared__ float sv[256 * KK];
    __shared__ int   si[256 * KK];
    __shared__ float wv[8 * KK];
    __shared__ int   wi[8 * KK];
    int g = blockIdx.x;
    const float* row = g_pd + (size_t)g * NN;
    int t = threadIdx.x;

    // each thread: local top-20 over its 32 strided elements
    float lv[KK]; int li[KK];
#pragma unroll
    for (int j = 0; j < KK; j++) { int m = t + j * 256; lv[j] = row[m]; li[j] = m; }
    float mn = CUDART_INF_F; int mp = 0;
#pragma unroll
    for (int j = 0; j < KK; j++) if (lv[j] < mn) { mn = lv[j]; mp = j; }
    for (int j = KK; j < 32; j++) {
        int m = t + j * 256; float v = row[m];
        if (v > mn) {
            lv[mp] = v; li[mp] = m;
            mn = CUDART_INF_F;
            for (int jj = 0; jj < KK; jj++) if (lv[jj] < mn) { mn = lv[jj]; mp = jj; }
        }
    }
    // sort descending (insertion)
    for (int i = 1; i < KK; i++) {
        float v = lv[i]; int id = li[i]; int j = i - 1;
        while (j >= 0 && lv[j] < v) { lv[j + 1] = lv[j]; li[j + 1] = li[j]; j--; }
        lv[j + 1] = v; li[j + 1] = id;
    }
    for (int j = 0; j < KK; j++) { sv[t * KK + j] = lv[j]; si[t * KK + j] = li[j]; }
    __syncthreads();

    int lane = t & 31, w = t >> 5;
    // warp merge: 32 sorted lists -> warp top-20
    {
        int h = 0; float myv = sv[t * KK];
        for (int r = 0; r < KK; r++) {
            float v = myv; int src = lane;
#pragma unroll
            for (int off = 16; off > 0; off >>= 1) {
                float ov = __shfl_xor_sync(0xffffffffu, v, off);
                int   os = __shfl_xor_sync(0xffffffffu, src, off);
                if (ov > v || (ov == v && os < src)) { v = ov; src = os; }
            }
            if (lane == src) {
                wv[w * KK + r] = v; wi[w * KK + r] = si[t * KK + h];
                h++;
                myv = (h < KK) ? sv[t * KK + h] : -CUDART_INF_F;
            }
        }
    }
    __syncthreads();
    // final merge: 8 warp lists -> top-20, warp 0
    if (w == 0) {
        int h = 0;
        float myv = (lane < 8) ? wv[lane * KK] : -CUDART_INF_F;
        for (int r = 0; r < KK; r++) {
            float v = myv; int src = lane;
#pragma unroll
            for (int off = 16; off > 0; off >>= 1) {
                float ov = __shfl_xor_sync(0xffffffffu, v, off);
                int   os = __shfl_xor_sync(0xffffffffu, src, off);
                if (ov > v || (ov == v && os < src)) { v = ov; src = os; }
            }
            if (lane == src) {
                g_idx[(size_t)g * KK + r] = wi[lane * KK + h];
                h++;
                myv = (h < KK && lane < 8) ? wv[lane * KK + h] : -CUDART_INF_F;
            }
        }
    }
}

// ---------------- K3: P = W1a·x_n ; T = (W1b - W1a)·x_n ----------------
__global__ __launch_bounds__(128) void k_pt(const float* __restrict__ W1) {
    extern __shared__ float sm[];
    float* Wt = sm;                // [128][129] transposed coeffs
    __shared__ float xr[64];
    int t = threadIdx.x;
    for (int s = t; s < 128 * 128; s += 128) {
        int d = s >> 7;            // row of W1
        int c = s & 127;           // == t -> conflict-free smem writes
        float wvv = W1[d * 128 + c];
        if (c >= 64) wvv -= W1[d * 128 + c - 64];
        Wt[c * 129 + d] = wvv;
    }
    __syncthreads();
    int g0 = blockIdx.x * 32;
    for (int nn = 0; nn < 32; nn++) {
        int g = g0 + nn;
        if (t < 64) xr[t] = g_xt[(size_t)g * CC + t];
        __syncthreads();
        float p = 0.f, tt = 0.f;
#pragma unroll
        for (int c = 0; c < 64; c++) {
            float xv = xr[c];
            p  = fmaf(Wt[c * 129 + t],        xv, p);
            tt = fmaf(Wt[(c + 64) * 129 + t], xv, tt);
        }
        g_pt[(size_t)g * 256 + t]       = p;
        g_pt[(size_t)g * 256 + 128 + t] = tt;
        __syncthreads();
    }
}

// ---------------- K4: gather + softmax_k + g-collapse + W2 matvec ----------------
__global__ __launch_bounds__(128) void k_out(const float* __restrict__ W2,
                                             float* __restrict__ out) {
    extern __shared__ float sm[];
    float* W2t = sm;               // [128][129] transposed W2
    __shared__ float gs[128];
    __shared__ float ctrs[64];
    __shared__ int   nid[KK];
    int t = threadIdx.x;
    for (int s = t; s < 128 * 128; s += 128) {
        int o = s >> 7; int c = s & 127;
        W2t[c * 129 + o] = W2[o * 128 + c];
    }
    __syncthreads();
    int g0 = blockIdx.x * 16;
    for (int nn = 0; nn < 16; nn++) {
        int g = g0 + nn;
        int b = g >> 13, n = g & (NN - 1);
        if (t < KK) nid[t] = g_idx[(size_t)g * KK + t];
        if (t < 64) ctrs[t] = g_xt[(size_t)g * CC + t];
        float tv = g_pt[(size_t)g * 256 + 128 + t];
        __syncthreads();

        float h[KK];
#pragma unroll
        for (int k = 0; k < KK; k++) {
            int ng = (b << 13) + nid[k];
            h[k] = g_pt[(size_t)ng * 256 + t] + tv;
        }
        float hm = -CUDART_INF_F;
#pragma unroll
        for (int k = 0; k < KK; k++) hm = fmaxf(hm, h[k]);
        float s = 0.f;
#pragma unroll
        for (int k = 0; k < KK; k++) { float e = __expf(h[k] - hm); s += e; h[k] = e; }
        float inv = 1.f / s;

        float gd;
        if (t < 64) {
            float c0 = ctrs[t];
            float a = 0.f;
#pragma unroll
            for (int k = 0; k < KK; k++) {
                int ng = (b << 13) + nid[k];
                a = fmaf(g_xt[(size_t)ng * CC + t] - c0, h[k], a);
            }
            gd = a * inv;
        } else {
            float sg = 0.f;
#pragma unroll
            for (int k = 0; k < KK; k++) sg += h[k];
            gd = ctrs[t - 64] * sg * inv;
        }
        gs[t] = gd;
        __syncthreads();

        float acc = 0.f;
#pragma unroll
        for (int c = 0; c < 128; c++) acc = fmaf(W2t[c * 129 + t], gs[c], acc);
        out[((size_t)b * OO + t) * NN + n] = acc;
        __syncthreads();
    }
}

// ---------------- launch ----------------
extern "C" void kernel_launch(void* const* d_in, const int* in_sizes, int n_in,
                              void* d_out, int out_size) {
    const float* x  = (const float*)d_in[0];
    const float* W1 = (const float*)d_in[1];
    const float* W2 = (const float*)d_in[2];
    float* out = (float*)d_out;

    cudaFuncSetAttribute(k_gemm, cudaFuncAttributeMaxDynamicSharedMemorySize, 64 * 1024);
    cudaFuncSetAttribute(k_pt,   cudaFuncAttributeMaxDynamicSharedMemorySize, 128 * 129 * 4);
    cudaFuncSetAttribute(k_out,  cudaFuncAttributeMaxDynamicSharedMemorySize, 128 * 129 * 4);

    k_prep<<<BN / 256, 256>>>(x);
    k_gemm<<<dim3(64, 64, 4), 256, 64 * 1024>>>(x);
    k_topk<<<BN, 256>>>();
    k_pt<<<BN / 32, 128, 128 * 129 * 4>>>(W1);
    k_out<<<BN / 16, 128, 128 * 129 * 4>>>(W2, out);
}

// round 4
// speedup vs baseline: 1.6840x; 1.6840x over previous
#include <cuda_runtime.h>
#include <cuda_bf16.h>
#include <math_constants.h>
#include <cstdint>

#define BB 4
#define CC 64
#define NN 8192
#define OO 128
#define KK 20
#define BN (BB*NN)

// ---------------- scratch (static device globals; no allocation) ----------------
__device__ float g_xt[(size_t)BN*CC];             // x transposed: [B*N, C]
__device__ float g_xx[BN];                        // squared norms
__device__ float g_pt[(size_t)BN*256];            // per point: P[128] then T[128]
__device__ int   g_idx[(size_t)BN*KK];            // top-20 neighbor indices
__device__ __nv_bfloat16 g_xs[(size_t)BN*128];    // per point: hi[64] then lo[64]

// ---------------- K0: transpose x + squared norms + bf16 hi/lo split ----------------
__global__ __launch_bounds__(256) void k_split(const float* __restrict__ x) {
    int g = blockIdx.x * 256 + threadIdx.x;
    int b = g >> 13, n = g & (NN - 1);
    const float* xb = x + (size_t)b * CC * NN + n;
    float acc = 0.f;
#pragma unroll
    for (int c = 0; c < CC; c++) {
        float v = xb[(size_t)c * NN];
        acc = fmaf(v, v, acc);
        g_xt[(size_t)g * CC + c] = v;
        __nv_bfloat16 hi = __float2bfloat16(v);
        __nv_bfloat16 lo = __float2bfloat16(v - __bfloat162float(hi));
        g_xs[(size_t)g * 128 + c]      = hi;
        g_xs[(size_t)g * 128 + 64 + c] = lo;
    }
    g_xx[g] = acc;
}

// ---------------- K1: fused distance (bf16 hi/lo mma.sync) + top-20 ----------------
// Block: 128 threads (4 warps). Each block owns 128 rows (n), loops over 64
// column tiles of 128 points. Per 128x32 chunk: HMMA -> smem stage -> per-row
// register top-20 update. The full pd matrix is never materialized.
//
// smem carve (bytes):
static constexpr int BS_OFF    = 0;        // Bs: 128 pts x (256B data + 16B pad) = 34816
static constexpr int STAGE_OFF = 34816;    // stage: 128 x 33 f32 = 16896
static constexpr int XXM_OFF   = 51712;    // xxm: 128 f32 = 512
static constexpr int SM_FUSED  = 52224;

__device__ __forceinline__ void mma16816(float* d, const uint32_t* a,
                                         uint32_t b0, uint32_t b1) {
    asm volatile(
        "mma.sync.aligned.m16n8k16.row.col.f32.bf16.bf16.f32 "
        "{%0,%1,%2,%3}, {%4,%5,%6,%7}, {%8,%9}, {%0,%1,%2,%3};"
        : "+f"(d[0]), "+f"(d[1]), "+f"(d[2]), "+f"(d[3])
        : "r"(a[0]), "r"(a[1]), "r"(a[2]), "r"(a[3]), "r"(b0), "r"(b1));
}

__global__ __launch_bounds__(128) void k_fused() {
    extern __shared__ char smem[];
    char*  smBs   = smem + BS_OFF;
    float* stage  = (float*)(smem + STAGE_OFF);
    float* xxm    = (float*)(smem + XXM_OFF);

    int t = threadIdx.x, lane = t & 31, wid = t >> 5;
    int b = blockIdx.y;
    int n0 = blockIdx.x << 7;

    // ---- load A fragments (this block's 128 rows) into registers, hi+lo ----
    // afr[h][mtile][ks][0..3]; h: 0=hi,1=lo
    uint32_t afr[2][2][4][4];
    {
        int rA = b * NN + n0 + wid * 32 + (lane >> 2);
#pragma unroll
        for (int h = 0; h < 2; h++)
#pragma unroll
            for (int m = 0; m < 2; m++)
#pragma unroll
                for (int ks = 0; ks < 4; ks++) {
                    int bk = h * 64 + ks * 16 + (lane & 3) * 2;
                    const __nv_bfloat16* pa = g_xs + (size_t)(rA + m * 16) * 128 + bk;
                    afr[h][m][ks][0] = *(const uint32_t*)pa;
                    afr[h][m][ks][1] = *(const uint32_t*)(pa + 8 * 128);
                    afr[h][m][ks][2] = *(const uint32_t*)(pa + 8);
                    afr[h][m][ks][3] = *(const uint32_t*)(pa + 8 * 128 + 8);
                }
    }

    // ---- per-row top-20 state (thread t owns row n0+t) ----
    float tv[KK]; int ti[KK];
#pragma unroll
    for (int q = 0; q < KK; q++) { tv[q] = -CUDART_INF_F; ti[q] = 0; }
    float thr = -CUDART_INF_F; int thrpos = 0;

    for (int mt = 0; mt < 64; mt++) {
        // load B tile: 128 points x 128 bf16 (256B each = 16 uint4) -> Bs
        const uint4* src = (const uint4*)(g_xs + (size_t)(b * NN + mt * 128) * 128);
#pragma unroll
        for (int i = t; i < 2048; i += 128) {
            int p = i >> 4, s = i & 15;
            *(uint4*)(smBs + p * 272 + s * 16) = src[i];
        }
        xxm[t] = g_xx[b * NN + mt * 128 + t];
        __syncthreads();

#pragma unroll 1
        for (int c4 = 0; c4 < 4; c4++) {
            float d[2][4][4];
#pragma unroll
            for (int m = 0; m < 2; m++)
#pragma unroll
                for (int nt = 0; nt < 4; nt++)
#pragma unroll
                    for (int q = 0; q < 4; q++) d[m][nt][q] = 0.f;

#pragma unroll
            for (int pass = 0; pass < 3; pass++) {
                const int Ap = (pass == 2) ? 1 : 0;
                const int Bp = (pass == 1) ? 1 : 0;
#pragma unroll
                for (int ks = 0; ks < 4; ks++) {
                    uint32_t bf[4][2];
#pragma unroll
                    for (int nt = 0; nt < 4; nt++) {
                        int n = c4 * 32 + nt * 8 + (lane >> 2);
                        int kb = Bp * 64 + ks * 16 + (lane & 3) * 2;
                        bf[nt][0] = *(const uint32_t*)(smBs + n * 272 + kb * 2);
                        bf[nt][1] = *(const uint32_t*)(smBs + n * 272 + (kb + 8) * 2);
                    }
#pragma unroll
                    for (int m = 0; m < 2; m++)
#pragma unroll
                        for (int nt = 0; nt < 4; nt++)
                            mma16816(d[m][nt], afr[Ap][m][ks], bf[nt][0], bf[nt][1]);
                }
            }

            // epilogue: stage[row][cj] = 2*dot - xxm[col]
#pragma unroll
            for (int m = 0; m < 2; m++)
#pragma unroll
                for (int nt = 0; nt < 4; nt++) {
                    int row = wid * 32 + m * 16 + (lane >> 2);
                    int cj  = nt * 8 + (lane & 3) * 2;
                    float xm0 = xxm[c4 * 32 + cj];
                    float xm1 = xxm[c4 * 32 + cj + 1];
                    stage[row * 33 + cj]           = 2.f * d[m][nt][0] - xm0;
                    stage[row * 33 + cj + 1]       = 2.f * d[m][nt][1] - xm1;
                    stage[(row + 8) * 33 + cj]     = 2.f * d[m][nt][2] - xm0;
                    stage[(row + 8) * 33 + cj + 1] = 2.f * d[m][nt][3] - xm1;
                }
            __syncthreads();

            // scan: thread t owns row t; 32 candidates
            int basecol = mt * 128 + c4 * 32;
#pragma unroll 8
            for (int j = 0; j < 32; j++) {
                float v = stage[t * 33 + j];
                if (v > thr) {
                    int col = basecol + j;
#pragma unroll
                    for (int q = 0; q < KK; q++)
                        if (q == thrpos) { tv[q] = v; ti[q] = col; }
                    thr = tv[0]; thrpos = 0;
#pragma unroll
                    for (int q = 1; q < KK; q++)
                        if (tv[q] < thr) { thr = tv[q]; thrpos = q; }
                }
            }
            __syncthreads();
        }
    }

    int g = b * NN + n0 + t;
#pragma unroll
    for (int q = 0; q < KK; q++) g_idx[(size_t)g * KK + q] = ti[q];
}

// ---------------- K3: P = W1a·x_n ; T = (W1b - W1a)·x_n ----------------
__global__ __launch_bounds__(128) void k_pt(const float* __restrict__ W1) {
    extern __shared__ float sm[];
    float* Wt = sm;
    __shared__ float xr[64];
    int t = threadIdx.x;
    for (int s = t; s < 128 * 128; s += 128) {
        int d = s >> 7, c = s & 127;
        float wvv = W1[d * 128 + c];
        if (c >= 64) wvv -= W1[d * 128 + c - 64];
        Wt[c * 129 + d] = wvv;
    }
    __syncthreads();
    int g0 = blockIdx.x * 32;
    for (int nn = 0; nn < 32; nn++) {
        int g = g0 + nn;
        if (t < 64) xr[t] = g_xt[(size_t)g * CC + t];
        __syncthreads();
        float p = 0.f, tt = 0.f;
#pragma unroll
        for (int c = 0; c < 64; c++) {
            float xv = xr[c];
            p  = fmaf(Wt[c * 129 + t],        xv, p);
            tt = fmaf(Wt[(c + 64) * 129 + t], xv, tt);
        }
        g_pt[(size_t)g * 256 + t]       = p;
        g_pt[(size_t)g * 256 + 128 + t] = tt;
        __syncthreads();
    }
}

// ---------------- K4: gather + softmax_k + g-collapse + W2 matvec ----------------
__global__ __launch_bounds__(128) void k_out(const float* __restrict__ W2,
                                             float* __restrict__ out) {
    extern __shared__ float sm[];
    float* W2t = sm;
    __shared__ float gs[128];
    __shared__ float ctrs[64];
    __shared__ int   nid[KK];
    int t = threadIdx.x;
    for (int s = t; s < 128 * 128; s += 128) {
        int o = s >> 7, c = s & 127;
        W2t[c * 129 + o] = W2[o * 128 + c];
    }
    __syncthreads();
    int g0 = blockIdx.x * 16;
    for (int nn = 0; nn < 16; nn++) {
        int g = g0 + nn;
        int b = g >> 13, n = g & (NN - 1);
        if (t < KK) nid[t] = g_idx[(size_t)g * KK + t];
        if (t < 64) ctrs[t] = g_xt[(size_t)g * CC + t];
        float tvv = g_pt[(size_t)g * 256 + 128 + t];
        __syncthreads();

        float h[KK];
#pragma unroll
        for (int k = 0; k < KK; k++) {
            int ng = (b << 13) + nid[k];
            h[k] = g_pt[(size_t)ng * 256 + t] + tvv;
        }
        float hm = -CUDART_INF_F;
#pragma unroll
        for (int k = 0; k < KK; k++) hm = fmaxf(hm, h[k]);
        float s = 0.f;
#pragma unroll
        for (int k = 0; k < KK; k++) { float e = __expf(h[k] - hm); s += e; h[k] = e; }
        float inv = 1.f / s;

        float gd;
        if (t < 64) {
            float c0 = ctrs[t];
            float a = 0.f;
#pragma unroll
            for (int k = 0; k < KK; k++) {
                int ng = (b << 13) + nid[k];
                a = fmaf(g_xt[(size_t)ng * CC + t] - c0, h[k], a);
            }
            gd = a * inv;
        } else {
            float sg = 0.f;
#pragma unroll
            for (int k = 0; k < KK; k++) sg += h[k];
            gd = ctrs[t - 64] * sg * inv;
        }
        gs[t] = gd;
        __syncthreads();

        float acc = 0.f;
#pragma unroll
        for (int c = 0; c < 128; c++) acc = fmaf(W2t[c * 129 + t], gs[c], acc);
        out[((size_t)b * OO + t) * NN + n] = acc;
        __syncthreads();
    }
}

// ---------------- launch ----------------
extern "C" void kernel_launch(void* const* d_in, const int* in_sizes, int n_in,
                              void* d_out, int out_size) {
    const float* x  = (const float*)d_in[0];
    const float* W1 = (const float*)d_in[1];
    const float* W2 = (const float*)d_in[2];
    float* out = (float*)d_out;

    cudaFuncSetAttribute(k_fused, cudaFuncAttributeMaxDynamicSharedMemorySize, SM_FUSED);
    cudaFuncSetAttribute(k_pt,    cudaFuncAttributeMaxDynamicSharedMemorySize, 128 * 129 * 4);
    cudaFuncSetAttribute(k_out,   cudaFuncAttributeMaxDynamicSharedMemorySize, 128 * 129 * 4);

    k_split<<<BN / 256, 256>>>(x);
    k_fused<<<dim3(64, 4), 128, SM_FUSED>>>();
    k_pt<<<BN / 32, 128, 128 * 129 * 4>>>(W1);
    k_out<<<BN / 16, 128, 128 * 129 * 4>>>(W2, out);
}